// round 12
// baseline (speedup 1.0000x reference)
#include <cuda_runtime.h>
#include <cuda_bf16.h>
#include <cstdint>

#define K_ORIG 4096
#define PACKN 10

// All harness tensors are FLOAT32-materialized (established R6-R8).
// Toolchain constraint (R10): virtual arch compute_100 -> NO tcgen05/TMA-tensor.
__device__ __align__(16) __nv_bfloat16 g_W[(size_t)4096 * 4096];
__device__ __align__(16) __nv_bfloat16 g_X[(size_t)2048 * 4096];

__device__ __forceinline__ float pick_scale(const int* c0, const int* c1) {
    float f0 = __int_as_float(*c0);
    float a0 = fabsf(f0);
    if (a0 > 1e-30f && a0 < 1e30f) return f0;
    return __int_as_float(*c1);
}

// ---------------------------------------------------------------------------
// Fused prologue: x f32->bf16 AND packed_w -> bf16 integer weights.
// ---------------------------------------------------------------------------
__global__ void prologue_kernel(const float4* __restrict__ xf, int n4,
                                const int* __restrict__ pw, int totalw,
                                int K_packs) {
    int idx = blockIdx.x * blockDim.x + threadIdx.x;

    if (idx < n4) {
        float4 v = xf[idx];
        __nv_bfloat162 lo = __floats2bfloat162_rn(v.x, v.y);
        __nv_bfloat162 hi = __floats2bfloat162_rn(v.z, v.w);
        uint2 u;
        u.x = *reinterpret_cast<uint32_t*>(&lo);
        u.y = *reinterpret_cast<uint32_t*>(&hi);
        *reinterpret_cast<uint2*>(g_X + (size_t)idx * 4) = u;
    }

    if (idx < totalw) {
        int n = idx / K_packs;
        int j = idx - n * K_packs;
        unsigned w = (unsigned)pw[idx];
        int k0 = j * PACKN;
        __nv_bfloat16* dst = g_W + (size_t)n * K_ORIG + k0;
#pragma unroll
        for (int p = 0; p < PACKN; p += 2) {
            int k = k0 + p;
            if (k < K_ORIG) {
                int c0 = (int)((w >> (3 * p)) & 7) - 2;
                int c1 = (int)((w >> (3 * p + 3)) & 7) - 2;
                __nv_bfloat162 v;
                v.x = __int2bfloat16_rn(c0);
                v.y = __int2bfloat16_rn(c1);
                *reinterpret_cast<__nv_bfloat162*>(dst + p) = v;
            }
        }
    }
}

// ---------------------------------------------------------------------------
// GEMM: y = bf16_round(scale*(X @ Wc^T) + bias) stored f32.
// BM=128 BN=128 BK=64, 256 threads (8 warps, 2x4), warp tile 64x32,
// 3-stage cp.async ring. __launch_bounds__(256,2): <=128 regs, 2 CTAs/SM so
// one CTA's barrier stalls overlap the other CTA's MMA issue.
// ---------------------------------------------------------------------------
#define BM 128
#define BN 128
#define BK 64
#define STAGES 3
#define ROW_BYTES 144
#define XSTAGE_BYTES (BM * ROW_BYTES)          // 18432
#define WSTAGE_BYTES (BN * ROW_BYTES)          // 18432
#define STAGE_BYTES (XSTAGE_BYTES + WSTAGE_BYTES)
#define SMEM_TOTAL (STAGES * STAGE_BYTES)      // 110592 -> 2 CTAs = 221184 B/SM

__device__ __forceinline__ void cp_async16(uint32_t dst, const void* src) {
    asm volatile("cp.async.cg.shared.global [%0], [%1], 16;\n" :: "r"(dst), "l"(src));
}
__device__ __forceinline__ void cp_commit() {
    asm volatile("cp.async.commit_group;\n" ::: "memory");
}
template <int Ng>
__device__ __forceinline__ void cp_wait() {
    asm volatile("cp.async.wait_group %0;\n" :: "n"(Ng) : "memory");
}

__global__ __launch_bounds__(256, 2) void penta_gemm_kernel(
    const int* __restrict__ sc_c0,
    const int* __restrict__ sc_c1,
    const float* __restrict__ bias,
    float* __restrict__ out,
    int M, int N)
{
    extern __shared__ char smem_raw[];
    const int K = K_ORIG;
    const int tid = threadIdx.x;
    const int lane = tid & 31;
    const int warp = tid >> 5;
    const int wm = warp >> 2;   // 0..1 : 64-row slab of M
    const int wn = warp & 3;    // 0..3 : 32-col slab of N
    const int bm = blockIdx.y * BM;
    const int bn = blockIdx.x * BN;
    const uint32_t sbase = (uint32_t)__cvta_generic_to_shared(smem_raw);

    float acc[4][4][4];
#pragma unroll
    for (int i = 0; i < 4; i++)
#pragma unroll
        for (int j = 0; j < 4; j++)
#pragma unroll
            for (int r = 0; r < 4; r++) acc[i][j][r] = 0.0f;

    auto load_stage = [&](int kt, int slot) {
        uint32_t xs = sbase + slot * STAGE_BYTES;
        uint32_t wsm = xs + XSTAGE_BYTES;
        const __nv_bfloat16* gx = g_X + (size_t)bm * K + kt * BK;
        const __nv_bfloat16* gw = g_W + (size_t)bn * K + kt * BK;
#pragma unroll
        for (int i = 0; i < 4; i++) {          // A+B: 1024 chunks each
            int cid = tid + i * 256;
            int r = cid >> 3;
            int c = cid & 7;
            cp_async16(xs + r * ROW_BYTES + c * 16, gx + (size_t)r * K + c * 8);
            cp_async16(wsm + r * ROW_BYTES + c * 16, gw + (size_t)r * K + c * 8);
        }
    };

    const int KT = K / BK;  // 64
#pragma unroll
    for (int s = 0; s < STAGES - 1; s++) { load_stage(s, s); cp_commit(); }

    for (int kt = 0; kt < KT; kt++) {
        cp_wait<STAGES - 2>();
        __syncthreads();
        int pf = kt + STAGES - 1;
        if (pf < KT) load_stage(pf, pf % STAGES);
        cp_commit();

        uint32_t xs = sbase + (kt % STAGES) * STAGE_BYTES;
        uint32_t wsm = xs + XSTAGE_BYTES;

#pragma unroll
        for (int ks = 0; ks < BK / 16; ks++) {
            uint32_t a[4][4];
#pragma unroll
            for (int mi = 0; mi < 4; mi++) {
                int r = wm * 64 + mi * 16 + (lane & 7) + ((lane >> 3) & 1) * 8;
                int ch = 2 * ks + (lane >> 4);
                uint32_t addr = xs + r * ROW_BYTES + ch * 16;
                asm volatile(
                    "ldmatrix.sync.aligned.m8n8.x4.shared.b16 {%0,%1,%2,%3}, [%4];"
                    : "=r"(a[mi][0]), "=r"(a[mi][1]), "=r"(a[mi][2]), "=r"(a[mi][3])
                    : "r"(addr));
            }
            uint32_t b[2][4];
#pragma unroll
            for (int bp = 0; bp < 2; bp++) {
                int rn = wn * 32 + bp * 16 + ((lane >> 4) & 1) * 8 + (lane & 7);
                int ch = 2 * ks + ((lane >> 3) & 1);
                uint32_t addr = wsm + rn * ROW_BYTES + ch * 16;
                asm volatile(
                    "ldmatrix.sync.aligned.m8n8.x4.shared.b16 {%0,%1,%2,%3}, [%4];"
                    : "=r"(b[bp][0]), "=r"(b[bp][1]), "=r"(b[bp][2]), "=r"(b[bp][3])
                    : "r"(addr));
            }
#pragma unroll
            for (int mi = 0; mi < 4; mi++) {
#pragma unroll
                for (int ni = 0; ni < 4; ni++) {
                    uint32_t b0 = b[ni >> 1][(ni & 1) * 2 + 0];
                    uint32_t b1 = b[ni >> 1][(ni & 1) * 2 + 1];
                    asm volatile(
                        "mma.sync.aligned.m16n8k16.row.col.f32.bf16.bf16.f32 "
                        "{%0,%1,%2,%3}, {%4,%5,%6,%7}, {%8,%9}, {%0,%1,%2,%3};"
                        : "+f"(acc[mi][ni][0]), "+f"(acc[mi][ni][1]),
                          "+f"(acc[mi][ni][2]), "+f"(acc[mi][ni][3])
                        : "r"(a[mi][0]), "r"(a[mi][1]), "r"(a[mi][2]), "r"(a[mi][3]),
                          "r"(b0), "r"(b1));
                }
            }
        }
    }

    // Epilogue: y = bf16_round(acc*scale + bias) stored as FLOAT32.
    const float sc = pick_scale(sc_c0, sc_c1);
#pragma unroll
    for (int ni = 0; ni < 4; ni++) {
        int n = bn + wn * 32 + ni * 8 + (lane & 3) * 2;
        float2 bv = *reinterpret_cast<const float2*>(bias + n);
#pragma unroll
        for (int mi = 0; mi < 4; mi++) {
            int m0 = bm + wm * 64 + mi * 16 + (lane >> 2);
            float2 v0, v1;
            v0.x = __bfloat162float(__float2bfloat16(acc[mi][ni][0] * sc + bv.x));
            v0.y = __bfloat162float(__float2bfloat16(acc[mi][ni][1] * sc + bv.y));
            v1.x = __bfloat162float(__float2bfloat16(acc[mi][ni][2] * sc + bv.x));
            v1.y = __bfloat162float(__float2bfloat16(acc[mi][ni][3] * sc + bv.y));
            *reinterpret_cast<float2*>(out + (size_t)m0 * N + n) = v0;
            *reinterpret_cast<float2*>(out + (size_t)(m0 + 8) * N + n) = v1;
        }
    }
}

// ---------------------------------------------------------------------------
extern "C" void kernel_launch(void* const* d_in, const int* in_sizes, int n_in,
                              void* d_out, int out_size) {
    int ix = -1, ipw = -1, ibias = -1;
    int ones[2] = {-1, -1};
    int n1 = 0;
    long long sx = -1, spw = -1;
    for (int i = 0; i < n_in; i++) {
        long long s = in_sizes[i];
        if (s > 100000) {
            if (s > sx) { ipw = ix; spw = sx; ix = i; sx = s; }
            else if (s > spw) { ipw = i; spw = s; }
        } else if (s > 8) {
            ibias = i;
        } else if (n1 < 2) {
            ones[n1++] = i;
        }
    }
    if (n1 == 1) ones[1] = ones[0];
    if (ix < 0 || ipw < 0 || ibias < 0 || n1 == 0) return;

    const float* xf = (const float*)d_in[ix];
    const int* pw = (const int*)d_in[ipw];
    const float* bias = (const float*)d_in[ibias];
    const int* sc0 = (const int*)d_in[ones[0]];
    const int* sc1 = (const int*)d_in[ones[1]];
    float* out = (float*)d_out;

    const int N = in_sizes[ibias];               // 4096
    const int K_packs = in_sizes[ipw] / N;       // 410
    const long long nx = in_sizes[ix];           // 8388608
    const int M = (int)(nx / K_ORIG);            // 2048
    const int totalw = N * K_packs;              // 1679360
    const int n4 = (int)(nx / 4);                // 2097152

    int pro_items = n4 > totalw ? n4 : totalw;
    prologue_kernel<<<(pro_items + 255) / 256, 256>>>(
        (const float4*)xf, n4, pw, totalw, K_packs);

    cudaFuncSetAttribute(penta_gemm_kernel,
                         cudaFuncAttributeMaxDynamicSharedMemorySize, SMEM_TOTAL);
    dim3 grid(N / BN, M / BM);
    penta_gemm_kernel<<<grid, 256, SMEM_TOTAL>>>(sc0, sc1, bias, out, M, N);
}

// round 13
// speedup vs baseline: 1.0927x; 1.0927x over previous
#include <cuda_runtime.h>
#include <cuda_bf16.h>
#include <cstdint>

#define K_ORIG 4096
#define PACKN 10

// All harness tensors are FLOAT32-materialized (established R6-R8).
// Toolchain constraint (R10): virtual arch compute_100 -> NO tcgen05/TMA-tensor.
__device__ __align__(16) __nv_bfloat16 g_W[(size_t)4096 * 4096];
__device__ __align__(16) __nv_bfloat16 g_X[(size_t)2048 * 4096];

__device__ __forceinline__ float pick_scale(const int* c0, const int* c1) {
    float f0 = __int_as_float(*c0);
    float a0 = fabsf(f0);
    if (a0 > 1e-30f && a0 < 1e30f) return f0;
    return __int_as_float(*c1);
}

// ---------------------------------------------------------------------------
// Fused prologue: x f32->bf16 AND packed_w -> bf16 integer weights.
// ---------------------------------------------------------------------------
__global__ void prologue_kernel(const float4* __restrict__ xf, int n4,
                                const int* __restrict__ pw, int totalw,
                                int K_packs) {
    int idx = blockIdx.x * blockDim.x + threadIdx.x;

    if (idx < n4) {
        float4 v = xf[idx];
        __nv_bfloat162 lo = __floats2bfloat162_rn(v.x, v.y);
        __nv_bfloat162 hi = __floats2bfloat162_rn(v.z, v.w);
        uint2 u;
        u.x = *reinterpret_cast<uint32_t*>(&lo);
        u.y = *reinterpret_cast<uint32_t*>(&hi);
        *reinterpret_cast<uint2*>(g_X + (size_t)idx * 4) = u;
    }

    if (idx < totalw) {
        int n = idx / K_packs;
        int j = idx - n * K_packs;
        unsigned w = (unsigned)pw[idx];
        int k0 = j * PACKN;
        __nv_bfloat16* dst = g_W + (size_t)n * K_ORIG + k0;
#pragma unroll
        for (int p = 0; p < PACKN; p += 2) {
            int k = k0 + p;
            if (k < K_ORIG) {
                int c0 = (int)((w >> (3 * p)) & 7) - 2;
                int c1 = (int)((w >> (3 * p + 3)) & 7) - 2;
                __nv_bfloat162 v;
                v.x = __int2bfloat16_rn(c0);
                v.y = __int2bfloat16_rn(c1);
                *reinterpret_cast<__nv_bfloat162*>(dst + p) = v;
            }
        }
    }
}

// ---------------------------------------------------------------------------
// GEMM: y = bf16_round(scale*(X @ Wc^T) + bias) stored f32.
// BM=128 BN=128 BK=64, 256 threads (8 warps, 2x4), warp tile 64x32,
// 3-stage cp.async ring + REGISTER DOUBLE-BUFFERED fragments: ldmatrix for
// step ks+1 issues while mma consumes step ks (removes ldmatrix->mma stall).
// ---------------------------------------------------------------------------
#define BM 128
#define BN 128
#define BK 64
#define STAGES 3
#define ROW_BYTES 144
#define XSTAGE_BYTES (BM * ROW_BYTES)          // 18432
#define WSTAGE_BYTES (BN * ROW_BYTES)          // 18432
#define STAGE_BYTES (XSTAGE_BYTES + WSTAGE_BYTES)
#define SMEM_TOTAL (STAGES * STAGE_BYTES)      // 110592

__device__ __forceinline__ void cp_async16(uint32_t dst, const void* src) {
    asm volatile("cp.async.cg.shared.global [%0], [%1], 16;\n" :: "r"(dst), "l"(src));
}
__device__ __forceinline__ void cp_commit() {
    asm volatile("cp.async.commit_group;\n" ::: "memory");
}
template <int Ng>
__device__ __forceinline__ void cp_wait() {
    asm volatile("cp.async.wait_group %0;\n" :: "n"(Ng) : "memory");
}

__global__ __launch_bounds__(256) void penta_gemm_kernel(
    const int* __restrict__ sc_c0,
    const int* __restrict__ sc_c1,
    const float* __restrict__ bias,
    float* __restrict__ out,
    int M, int N)
{
    extern __shared__ char smem_raw[];
    const int K = K_ORIG;
    const int tid = threadIdx.x;
    const int lane = tid & 31;
    const int warp = tid >> 5;
    const int wm = warp >> 2;   // 0..1 : 64-row slab of M
    const int wn = warp & 3;    // 0..3 : 32-col slab of N
    const int bm = blockIdx.y * BM;
    const int bn = blockIdx.x * BN;
    const uint32_t sbase = (uint32_t)__cvta_generic_to_shared(smem_raw);

    float acc[4][4][4];
#pragma unroll
    for (int i = 0; i < 4; i++)
#pragma unroll
        for (int j = 0; j < 4; j++)
#pragma unroll
            for (int r = 0; r < 4; r++) acc[i][j][r] = 0.0f;

    auto load_stage = [&](int kt, int slot) {
        uint32_t xs = sbase + slot * STAGE_BYTES;
        uint32_t wsm = xs + XSTAGE_BYTES;
        const __nv_bfloat16* gx = g_X + (size_t)bm * K + kt * BK;
        const __nv_bfloat16* gw = g_W + (size_t)bn * K + kt * BK;
#pragma unroll
        for (int i = 0; i < 4; i++) {
            int cid = tid + i * 256;
            int r = cid >> 3;
            int c = cid & 7;
            cp_async16(xs + r * ROW_BYTES + c * 16, gx + (size_t)r * K + c * 8);
            cp_async16(wsm + r * ROW_BYTES + c * 16, gw + (size_t)r * K + c * 8);
        }
    };

    // Fragment load for (stage slot, ks) into the given register buffers.
    auto ld_frags = [&](int slot, int ks, uint32_t a[4][4], uint32_t b[2][4]) {
        uint32_t xs = sbase + slot * STAGE_BYTES;
        uint32_t wsm = xs + XSTAGE_BYTES;
#pragma unroll
        for (int mi = 0; mi < 4; mi++) {
            int r = wm * 64 + mi * 16 + (lane & 7) + ((lane >> 3) & 1) * 8;
            int ch = 2 * ks + (lane >> 4);
            uint32_t addr = xs + r * ROW_BYTES + ch * 16;
            asm volatile(
                "ldmatrix.sync.aligned.m8n8.x4.shared.b16 {%0,%1,%2,%3}, [%4];"
                : "=r"(a[mi][0]), "=r"(a[mi][1]), "=r"(a[mi][2]), "=r"(a[mi][3])
                : "r"(addr));
        }
#pragma unroll
        for (int bp = 0; bp < 2; bp++) {
            int rn = wn * 32 + bp * 16 + ((lane >> 4) & 1) * 8 + (lane & 7);
            int ch = 2 * ks + ((lane >> 3) & 1);
            uint32_t addr = wsm + rn * ROW_BYTES + ch * 16;
            asm volatile(
                "ldmatrix.sync.aligned.m8n8.x4.shared.b16 {%0,%1,%2,%3}, [%4];"
                : "=r"(b[bp][0]), "=r"(b[bp][1]), "=r"(b[bp][2]), "=r"(b[bp][3])
                : "r"(addr));
        }
    };

    auto do_mma = [&](uint32_t a[4][4], uint32_t b[2][4]) {
#pragma unroll
        for (int mi = 0; mi < 4; mi++) {
#pragma unroll
            for (int ni = 0; ni < 4; ni++) {
                uint32_t b0 = b[ni >> 1][(ni & 1) * 2 + 0];
                uint32_t b1 = b[ni >> 1][(ni & 1) * 2 + 1];
                asm volatile(
                    "mma.sync.aligned.m16n8k16.row.col.f32.bf16.bf16.f32 "
                    "{%0,%1,%2,%3}, {%4,%5,%6,%7}, {%8,%9}, {%0,%1,%2,%3};"
                    : "+f"(acc[mi][ni][0]), "+f"(acc[mi][ni][1]),
                      "+f"(acc[mi][ni][2]), "+f"(acc[mi][ni][3])
                    : "r"(a[mi][0]), "r"(a[mi][1]), "r"(a[mi][2]), "r"(a[mi][3]),
                      "r"(b0), "r"(b1));
            }
        }
    };

    const int KT = K / BK;  // 64

    // Preload stages 0 and 1.
    load_stage(0, 0); cp_commit();
    load_stage(1, 1); cp_commit();
    cp_wait<1>();               // g0 complete
    __syncthreads();

    uint32_t a_buf[2][4][4], b_buf[2][2][4];
    ld_frags(0, 0, a_buf[0], b_buf[0]);   // stage 0, ks 0

    for (int kt = 0; kt < KT; kt++) {
        // Retire all readers of slot (kt+2)%3's old data, then refill it.
        __syncthreads();
        if (kt + 2 < KT) {
            load_stage(kt + 2, (kt + 2) % STAGES);
            cp_commit();
            cp_wait<1>();       // pending {g_{kt+1}, g_{kt+2}} -> g_{kt+1} done
        } else {
            cp_wait<0>();       // tail: everything (incl. g_{KT-1}) done
        }

        const int s = kt % STAGES;
#pragma unroll
        for (int ks = 0; ks < BK / 16; ks++) {
            const int cur = ks & 1;
            if (ks < 3) {
                ld_frags(s, ks + 1, a_buf[cur ^ 1], b_buf[cur ^ 1]);
            } else if (kt + 1 < KT) {
                // boundary: next stage's ks=0 (its group proven complete above)
                ld_frags((kt + 1) % STAGES, 0, a_buf[cur ^ 1], b_buf[cur ^ 1]);
            }
            do_mma(a_buf[cur], b_buf[cur]);
        }
    }

    // Epilogue: y = bf16_round(acc*scale + bias) stored as FLOAT32.
    const float sc = pick_scale(sc_c0, sc_c1);
#pragma unroll
    for (int ni = 0; ni < 4; ni++) {
        int n = bn + wn * 32 + ni * 8 + (lane & 3) * 2;
        float2 bv = *reinterpret_cast<const float2*>(bias + n);
#pragma unroll
        for (int mi = 0; mi < 4; mi++) {
            int m0 = bm + wm * 64 + mi * 16 + (lane >> 2);
            float2 v0, v1;
            v0.x = __bfloat162float(__float2bfloat16(acc[mi][ni][0] * sc + bv.x));
            v0.y = __bfloat162float(__float2bfloat16(acc[mi][ni][1] * sc + bv.y));
            v1.x = __bfloat162float(__float2bfloat16(acc[mi][ni][2] * sc + bv.x));
            v1.y = __bfloat162float(__float2bfloat16(acc[mi][ni][3] * sc + bv.y));
            *reinterpret_cast<float2*>(out + (size_t)m0 * N + n) = v0;
            *reinterpret_cast<float2*>(out + (size_t)(m0 + 8) * N + n) = v1;
        }
    }
}

// ---------------------------------------------------------------------------
extern "C" void kernel_launch(void* const* d_in, const int* in_sizes, int n_in,
                              void* d_out, int out_size) {
    int ix = -1, ipw = -1, ibias = -1;
    int ones[2] = {-1, -1};
    int n1 = 0;
    long long sx = -1, spw = -1;
    for (int i = 0; i < n_in; i++) {
        long long s = in_sizes[i];
        if (s > 100000) {
            if (s > sx) { ipw = ix; spw = sx; ix = i; sx = s; }
            else if (s > spw) { ipw = i; spw = s; }
        } else if (s > 8) {
            ibias = i;
        } else if (n1 < 2) {
            ones[n1++] = i;
        }
    }
    if (n1 == 1) ones[1] = ones[0];
    if (ix < 0 || ipw < 0 || ibias < 0 || n1 == 0) return;

    const float* xf = (const float*)d_in[ix];
    const int* pw = (const int*)d_in[ipw];
    const float* bias = (const float*)d_in[ibias];
    const int* sc0 = (const int*)d_in[ones[0]];
    const int* sc1 = (const int*)d_in[ones[1]];
    float* out = (float*)d_out;

    const int N = in_sizes[ibias];               // 4096
    const int K_packs = in_sizes[ipw] / N;       // 410
    const long long nx = in_sizes[ix];           // 8388608
    const int M = (int)(nx / K_ORIG);            // 2048
    const int totalw = N * K_packs;              // 1679360
    const int n4 = (int)(nx / 4);                // 2097152

    int pro_items = n4 > totalw ? n4 : totalw;
    prologue_kernel<<<(pro_items + 255) / 256, 256>>>(
        (const float4*)xf, n4, pw, totalw, K_packs);

    cudaFuncSetAttribute(penta_gemm_kernel,
                         cudaFuncAttributeMaxDynamicSharedMemorySize, SMEM_TOTAL);
    dim3 grid(N / BN, M / BM);
    penta_gemm_kernel<<<grid, 256, SMEM_TOTAL>>>(sc0, sc1, bias, out, M, N);
}

// round 14
// speedup vs baseline: 1.1338x; 1.0376x over previous
#include <cuda_runtime.h>
#include <cuda_bf16.h>
#include <cstdint>

#define K_ORIG 4096
#define PACKN 10

// All harness tensors are FLOAT32-materialized (established R6-R8).
// Toolchain constraint (R10): virtual arch compute_100 -> NO tcgen05/TMA-tensor.
__device__ __align__(16) __nv_bfloat16 g_W[(size_t)4096 * 4096];
__device__ __align__(16) __nv_bfloat16 g_X[(size_t)2048 * 4096];

__device__ __forceinline__ float pick_scale(const int* c0, const int* c1) {
    float f0 = __int_as_float(*c0);
    float a0 = fabsf(f0);
    if (a0 > 1e-30f && a0 < 1e30f) return f0;
    return __int_as_float(*c1);
}

// ---------------------------------------------------------------------------
// Fused prologue: x f32->bf16 AND packed_w -> bf16 integer weights.
// ---------------------------------------------------------------------------
__global__ void prologue_kernel(const float4* __restrict__ xf, int n4,
                                const int* __restrict__ pw, int totalw,
                                int K_packs) {
    int idx = blockIdx.x * blockDim.x + threadIdx.x;

    if (idx < n4) {
        float4 v = xf[idx];
        __nv_bfloat162 lo = __floats2bfloat162_rn(v.x, v.y);
        __nv_bfloat162 hi = __floats2bfloat162_rn(v.z, v.w);
        uint2 u;
        u.x = *reinterpret_cast<uint32_t*>(&lo);
        u.y = *reinterpret_cast<uint32_t*>(&hi);
        *reinterpret_cast<uint2*>(g_X + (size_t)idx * 4) = u;
    }

    if (idx < totalw) {
        int n = idx / K_packs;
        int j = idx - n * K_packs;
        unsigned w = (unsigned)pw[idx];
        int k0 = j * PACKN;
        __nv_bfloat16* dst = g_W + (size_t)n * K_ORIG + k0;
#pragma unroll
        for (int p = 0; p < PACKN; p += 2) {
            int k = k0 + p;
            if (k < K_ORIG) {
                int c0 = (int)((w >> (3 * p)) & 7) - 2;
                int c1 = (int)((w >> (3 * p + 3)) & 7) - 2;
                __nv_bfloat162 v;
                v.x = __int2bfloat16_rn(c0);
                v.y = __int2bfloat16_rn(c1);
                *reinterpret_cast<__nv_bfloat162*>(dst + p) = v;
            }
        }
    }
}

// ---------------------------------------------------------------------------
// GEMM: y = bf16_round(scale*(X @ Wc^T) + bias) stored f32.
// BM=128 BN=256 BK=64, 256 threads (8 warps, 2x4), WARP TILE 64x64
// (halves smem fragment traffic per FLOP; L1 was the co-binder at 47.8%).
// 3-stage cp.async ring + register double-buffered fragments.
// RACE FIX vs R13: cp_wait + __syncthreads at the ks==3 boundary BEFORE the
// cross-stage fragment prefetch (publishes all threads' cp.async writes).
// ---------------------------------------------------------------------------
#define BM 128
#define BN 256
#define BK 64
#define STAGES 3
#define ROW_BYTES 144
#define XSTAGE_BYTES (BM * ROW_BYTES)          // 18432
#define WSTAGE_BYTES (BN * ROW_BYTES)          // 36864
#define STAGE_BYTES (XSTAGE_BYTES + WSTAGE_BYTES)  // 55296
#define SMEM_TOTAL (STAGES * STAGE_BYTES)      // 165888

__device__ __forceinline__ void cp_async16(uint32_t dst, const void* src) {
    asm volatile("cp.async.cg.shared.global [%0], [%1], 16;\n" :: "r"(dst), "l"(src));
}
__device__ __forceinline__ void cp_commit() {
    asm volatile("cp.async.commit_group;\n" ::: "memory");
}
template <int Ng>
__device__ __forceinline__ void cp_wait() {
    asm volatile("cp.async.wait_group %0;\n" :: "n"(Ng) : "memory");
}

__global__ __launch_bounds__(256) void penta_gemm_kernel(
    const int* __restrict__ sc_c0,
    const int* __restrict__ sc_c1,
    const float* __restrict__ bias,
    float* __restrict__ out,
    int M, int N)
{
    extern __shared__ char smem_raw[];
    const int K = K_ORIG;
    const int tid = threadIdx.x;
    const int lane = tid & 31;
    const int warp = tid >> 5;
    const int wm = warp >> 2;   // 0..1 : 64-row slab of M
    const int wn = warp & 3;    // 0..3 : 64-col slab of N
    const int bm = blockIdx.y * BM;
    const int bn = blockIdx.x * BN;
    const uint32_t sbase = (uint32_t)__cvta_generic_to_shared(smem_raw);

    float acc[4][8][4];
#pragma unroll
    for (int i = 0; i < 4; i++)
#pragma unroll
        for (int j = 0; j < 8; j++)
#pragma unroll
            for (int r = 0; r < 4; r++) acc[i][j][r] = 0.0f;

    auto load_stage = [&](int kt, int slot) {
        uint32_t xs = sbase + slot * STAGE_BYTES;
        uint32_t wsm = xs + XSTAGE_BYTES;
        const __nv_bfloat16* gx = g_X + (size_t)bm * K + kt * BK;
        const __nv_bfloat16* gw = g_W + (size_t)bn * K + kt * BK;
#pragma unroll
        for (int i = 0; i < 4; i++) {          // A: 1024 chunks
            int cid = tid + i * 256;
            int r = cid >> 3;
            int c = cid & 7;
            cp_async16(xs + r * ROW_BYTES + c * 16, gx + (size_t)r * K + c * 8);
        }
#pragma unroll
        for (int i = 0; i < 8; i++) {          // B: 2048 chunks
            int cid = tid + i * 256;
            int r = cid >> 3;
            int c = cid & 7;
            cp_async16(wsm + r * ROW_BYTES + c * 16, gw + (size_t)r * K + c * 8);
        }
    };

    auto ld_frags = [&](int slot, int ks, uint32_t a[4][4], uint32_t b[4][4]) {
        uint32_t xs = sbase + slot * STAGE_BYTES;
        uint32_t wsm = xs + XSTAGE_BYTES;
#pragma unroll
        for (int mi = 0; mi < 4; mi++) {
            int r = wm * 64 + mi * 16 + (lane & 7) + ((lane >> 3) & 1) * 8;
            int ch = 2 * ks + (lane >> 4);
            uint32_t addr = xs + r * ROW_BYTES + ch * 16;
            asm volatile(
                "ldmatrix.sync.aligned.m8n8.x4.shared.b16 {%0,%1,%2,%3}, [%4];"
                : "=r"(a[mi][0]), "=r"(a[mi][1]), "=r"(a[mi][2]), "=r"(a[mi][3])
                : "r"(addr));
        }
#pragma unroll
        for (int bp = 0; bp < 4; bp++) {
            int rn = wn * 64 + bp * 16 + ((lane >> 4) & 1) * 8 + (lane & 7);
            int ch = 2 * ks + ((lane >> 3) & 1);
            uint32_t addr = wsm + rn * ROW_BYTES + ch * 16;
            asm volatile(
                "ldmatrix.sync.aligned.m8n8.x4.shared.b16 {%0,%1,%2,%3}, [%4];"
                : "=r"(b[bp][0]), "=r"(b[bp][1]), "=r"(b[bp][2]), "=r"(b[bp][3])
                : "r"(addr));
        }
    };

    auto do_mma = [&](uint32_t a[4][4], uint32_t b[4][4]) {
#pragma unroll
        for (int mi = 0; mi < 4; mi++) {
#pragma unroll
            for (int ni = 0; ni < 8; ni++) {
                uint32_t b0 = b[ni >> 1][(ni & 1) * 2 + 0];
                uint32_t b1 = b[ni >> 1][(ni & 1) * 2 + 1];
                asm volatile(
                    "mma.sync.aligned.m16n8k16.row.col.f32.bf16.bf16.f32 "
                    "{%0,%1,%2,%3}, {%4,%5,%6,%7}, {%8,%9}, {%0,%1,%2,%3};"
                    : "+f"(acc[mi][ni][0]), "+f"(acc[mi][ni][1]),
                      "+f"(acc[mi][ni][2]), "+f"(acc[mi][ni][3])
                    : "r"(a[mi][0]), "r"(a[mi][1]), "r"(a[mi][2]), "r"(a[mi][3]),
                      "r"(b0), "r"(b1));
            }
        }
    };

    const int KT = K / BK;  // 64

    load_stage(0, 0); cp_commit();
    load_stage(1, 1); cp_commit();
    cp_wait<1>();                    // g0 complete
    __syncthreads();                 // ...and visible to all

    uint32_t a_buf[2][4][4], b_buf[2][4][4];
    ld_frags(0, 0, a_buf[0], b_buf[0]);

    for (int kt = 0; kt < KT; kt++) {
        // Refill slot (kt+2)%3. Its old data (stage kt-1) was last read before
        // the ks==3 barrier of iteration kt-1 -> safe to overwrite.
        if (kt + 2 < KT) { load_stage(kt + 2, (kt + 2) % STAGES); cp_commit(); }

        const int s = kt % STAGES;
#pragma unroll
        for (int ks = 0; ks < BK / 16; ks++) {
            const int cur = ks & 1;
            if (ks < 3) {
                ld_frags(s, ks + 1, a_buf[cur ^ 1], b_buf[cur ^ 1]);
            } else {
                // Publish stage kt+1 to ALL threads before cross-stage read.
                if (kt + 2 < KT) cp_wait<1>(); else cp_wait<0>();
                __syncthreads();
                if (kt + 1 < KT)
                    ld_frags((kt + 1) % STAGES, 0, a_buf[cur ^ 1], b_buf[cur ^ 1]);
            }
            do_mma(a_buf[cur], b_buf[cur]);
        }
    }

    // Epilogue: y = bf16_round(acc*scale + bias) stored as FLOAT32.
    const float sc = pick_scale(sc_c0, sc_c1);
#pragma unroll
    for (int ni = 0; ni < 8; ni++) {
        int n = bn + wn * 64 + ni * 8 + (lane & 3) * 2;
        float2 bv = *reinterpret_cast<const float2*>(bias + n);
#pragma unroll
        for (int mi = 0; mi < 4; mi++) {
            int m0 = bm + wm * 64 + mi * 16 + (lane >> 2);
            float2 v0, v1;
            v0.x = __bfloat162float(__float2bfloat16(acc[mi][ni][0] * sc + bv.x));
            v0.y = __bfloat162float(__float2bfloat16(acc[mi][ni][1] * sc + bv.y));
            v1.x = __bfloat162float(__float2bfloat16(acc[mi][ni][2] * sc + bv.x));
            v1.y = __bfloat162float(__float2bfloat16(acc[mi][ni][3] * sc + bv.y));
            *reinterpret_cast<float2*>(out + (size_t)m0 * N + n) = v0;
            *reinterpret_cast<float2*>(out + (size_t)(m0 + 8) * N + n) = v1;
        }
    }
}

// ---------------------------------------------------------------------------
extern "C" void kernel_launch(void* const* d_in, const int* in_sizes, int n_in,
                              void* d_out, int out_size) {
    int ix = -1, ipw = -1, ibias = -1;
    int ones[2] = {-1, -1};
    int n1 = 0;
    long long sx = -1, spw = -1;
    for (int i = 0; i < n_in; i++) {
        long long s = in_sizes[i];
        if (s > 100000) {
            if (s > sx) { ipw = ix; spw = sx; ix = i; sx = s; }
            else if (s > spw) { ipw = i; spw = s; }
        } else if (s > 8) {
            ibias = i;
        } else if (n1 < 2) {
            ones[n1++] = i;
        }
    }
    if (n1 == 1) ones[1] = ones[0];
    if (ix < 0 || ipw < 0 || ibias < 0 || n1 == 0) return;

    const float* xf = (const float*)d_in[ix];
    const int* pw = (const int*)d_in[ipw];
    const float* bias = (const float*)d_in[ibias];
    const int* sc0 = (const int*)d_in[ones[0]];
    const int* sc1 = (const int*)d_in[ones[1]];
    float* out = (float*)d_out;

    const int N = in_sizes[ibias];               // 4096
    const int K_packs = in_sizes[ipw] / N;       // 410
    const long long nx = in_sizes[ix];           // 8388608
    const int M = (int)(nx / K_ORIG);            // 2048
    const int totalw = N * K_packs;              // 1679360
    const int n4 = (int)(nx / 4);                // 2097152

    int pro_items = n4 > totalw ? n4 : totalw;
    prologue_kernel<<<(pro_items + 255) / 256, 256>>>(
        (const float4*)xf, n4, pw, totalw, K_packs);

    cudaFuncSetAttribute(penta_gemm_kernel,
                         cudaFuncAttributeMaxDynamicSharedMemorySize, SMEM_TOTAL);
    dim3 grid(N / BN, M / BM);
    penta_gemm_kernel<<<grid, 256, SMEM_TOTAL>>>(sc0, sc1, bias, out, M, N);
}